// round 3
// baseline (speedup 1.0000x reference)
#include <cuda_runtime.h>
#include <stdint.h>

#define BB   8
#define NA   3
#define NC   80
#define HH   160
#define WW   160
#define HW   (HH*WW)        // 25600
#define NN   (NA*HW)        // 76800
#define TOPK 100
#define NBINS 2048
#define CAP  1024

// ---------------- device scratch (no allocations allowed) ----------------
__device__ float    g_scores[BB*NN];
__device__ uint8_t  g_cls[BB*NN];
__device__ int      g_hist[BB*NBINS];

__device__ __forceinline__ float sigmoidf_(float x) {
    return 1.0f / (1.0f + expf(-x));
}

// ---------------- kernel 0: zero histograms ----------------
__global__ void zero_hist_kernel() {
    int i = blockIdx.x * blockDim.x + threadIdx.x;
    if (i < BB * NBINS) g_hist[i] = 0;
}

// ---------------- kernel 1: score + argmax class + level-1 histogram ----------------
// grid is exactly BB*NN/4/256 = 600 blocks; each block covers 1024 cells of ONE batch.
__global__ void __launch_bounds__(256) score_kernel(const float* __restrict__ obj,
                                                    const float* __restrict__ quality,
                                                    const float* __restrict__ cls) {
    __shared__ int sh[NBINS];
    for (int i = threadIdx.x; i < NBINS; i += 256) sh[i] = 0;
    __syncthreads();

    int t  = blockIdx.x * blockDim.x + threadIdx.x;    // quad index
    int c0 = t * 4;                                    // base cell index
    int b   = c0 / NN;
    int r   = c0 - b * NN;
    int a   = r / HW;
    int pix = r - a * HW;                              // multiple of 4

    const float4* cbase = (const float4*)(cls + ((size_t)(b * NA + a) * NC) * HW + pix);
    float m0 = -1e30f, m1 = -1e30f, m2 = -1e30f, m3 = -1e30f;
    int   i0 = 0, i1 = 0, i2 = 0, i3 = 0;
    #pragma unroll 8
    for (int c = 0; c < NC; c++) {
        float4 v = cbase[c * (HW / 4)];
        if (v.x > m0) { m0 = v.x; i0 = c; }
        if (v.y > m1) { m1 = v.y; i1 = c; }
        if (v.z > m2) { m2 = v.z; i2 = c; }
        if (v.w > m3) { m3 = v.w; i3 = c; }
    }

    int oq = (b * NA + a) * HW + pix;
    float4 ov = *(const float4*)(obj + oq);
    float4 qv = *(const float4*)(quality + oq);

    float4 s;
    s.x = sigmoidf_(ov.x) * sigmoidf_(qv.x) * sigmoidf_(m0);
    s.y = sigmoidf_(ov.y) * sigmoidf_(qv.y) * sigmoidf_(m1);
    s.z = sigmoidf_(ov.z) * sigmoidf_(qv.z) * sigmoidf_(m2);
    s.w = sigmoidf_(ov.w) * sigmoidf_(qv.w) * sigmoidf_(m3);

    *(float4*)(g_scores + c0) = s;
    *(uchar4*)(g_cls + c0) = make_uchar4((uint8_t)i0, (uint8_t)i1, (uint8_t)i2, (uint8_t)i3);

    // level-1 histogram (top 11 bits; scores in (0,1) so sign bit is 0)
    atomicAdd(&sh[__float_as_uint(s.x) >> 21], 1);
    atomicAdd(&sh[__float_as_uint(s.y) >> 21], 1);
    atomicAdd(&sh[__float_as_uint(s.z) >> 21], 1);
    atomicAdd(&sh[__float_as_uint(s.w) >> 21], 1);
    __syncthreads();

    // merge nonzero bins to the per-batch global histogram
    for (int i = threadIdx.x; i < NBINS; i += 256) {
        int v = sh[i];
        if (v) atomicAdd(&g_hist[b * NBINS + i], v);
    }
}

// ---------------- kernel 2: per-batch top-100 + box decode ----------------
__global__ void __launch_bounds__(1024) topk_kernel(const float* __restrict__ box,
                                                    const float* __restrict__ anchors,
                                                    float* __restrict__ out) {
    __shared__ int                sh[NBINS];
    __shared__ unsigned long long buf[CAP];
    __shared__ int s_cnt, s_t, s_chi, s_tot, s_u;

    int b   = blockIdx.x;
    int tid = threadIdx.x;

    // ---- level-1 suffix scan over the prebuilt histogram ----
    sh[tid]        = g_hist[b * NBINS + tid];
    sh[tid + 1024] = g_hist[b * NBINS + tid + 1024];
    __syncthreads();
    #pragma unroll
    for (int d = 1; d < NBINS; d <<= 1) {
        int v0 = (tid + d < NBINS) ? sh[tid + d] : 0;
        int v1 = (tid + 1024 + d < NBINS) ? sh[tid + 1024 + d] : 0;
        __syncthreads();
        sh[tid] += v0;
        sh[tid + 1024] += v1;
        __syncthreads();
    }
    // crossing bin: largest i with S[i] >= TOPK
    {
        int i = tid;
        if (sh[i] >= TOPK && (i == NBINS - 1 || sh[i + 1] < TOPK)) {
            s_t = i; s_tot = sh[i]; s_chi = (i < NBINS - 1) ? sh[i + 1] : 0;
        }
        i = tid + 1024;
        if (sh[i] >= TOPK && (i == NBINS - 1 || sh[i + 1] < TOPK)) {
            s_t = i; s_tot = sh[i]; s_chi = (i < NBINS - 1) ? sh[i + 1] : 0;
        }
        if (tid == 0) s_cnt = 0;
    }
    __syncthreads();
    unsigned t1 = (unsigned)s_t;
    int cnt_tot = s_tot;
    int chi     = s_chi;

    const float4* sc4 = (const float4*)(g_scores + (size_t)b * NN);
    const float*  sc  = g_scores + (size_t)b * NN;

    if (cnt_tot <= CAP) {
        // ---- FAST PATH: exact candidate count known to fit; single collect scan ----
        for (int i = tid; i < NN / 4; i += 1024) {
            float4 v = sc4[i];
            unsigned bx = __float_as_uint(v.x);
            unsigned by = __float_as_uint(v.y);
            unsigned bz = __float_as_uint(v.z);
            unsigned bw = __float_as_uint(v.w);
            int base = i * 4;
            if ((bx >> 21) >= t1) buf[atomicAdd(&s_cnt, 1)] = (((unsigned long long)bx) << 17) | (unsigned long long)(0x1FFFFu - (unsigned)(base + 0));
            if ((by >> 21) >= t1) buf[atomicAdd(&s_cnt, 1)] = (((unsigned long long)by) << 17) | (unsigned long long)(0x1FFFFu - (unsigned)(base + 1));
            if ((bz >> 21) >= t1) buf[atomicAdd(&s_cnt, 1)] = (((unsigned long long)bz) << 17) | (unsigned long long)(0x1FFFFu - (unsigned)(base + 2));
            if ((bw >> 21) >= t1) buf[atomicAdd(&s_cnt, 1)] = (((unsigned long long)bw) << 17) | (unsigned long long)(0x1FFFFu - (unsigned)(base + 3));
        }
    } else {
        // ---- SLOW PATH (rare): level-2 refine on the boundary bin ----
        sh[tid] = 0; sh[tid + 1024] = 0;
        __syncthreads();
        for (int i = tid; i < NN; i += 1024) {
            unsigned bits = __float_as_uint(sc[i]);
            if ((bits >> 21) == t1) atomicAdd(&sh[(bits >> 10) & (NBINS - 1)], 1);
        }
        __syncthreads();
        #pragma unroll
        for (int d = 1; d < NBINS; d <<= 1) {
            int v0 = (tid + d < NBINS) ? sh[tid + d] : 0;
            int v1 = (tid + 1024 + d < NBINS) ? sh[tid + 1024 + d] : 0;
            __syncthreads();
            sh[tid] += v0;
            sh[tid + 1024] += v1;
            __syncthreads();
        }
        {
            int i = tid;
            if (chi + sh[i] >= TOPK && (i == NBINS - 1 || chi + sh[i + 1] < TOPK)) s_u = i;
            i = tid + 1024;
            if (chi + sh[i] >= TOPK && (i == NBINS - 1 || chi + sh[i + 1] < TOPK)) s_u = i;
        }
        __syncthreads();
        unsigned thr22 = (t1 << 11) | (unsigned)s_u;
        for (int i = tid; i < NN; i += 1024) {
            unsigned bits = __float_as_uint(sc[i]);
            if ((bits >> 10) >= thr22) {
                int p = atomicAdd(&s_cnt, 1);
                if (p < CAP)
                    buf[p] = (((unsigned long long)bits) << 17) |
                             (unsigned long long)(0x1FFFFu - (unsigned)i);
            }
        }
    }
    __syncthreads();
    int cnt = s_cnt < CAP ? s_cnt : CAP;

    // ---- rank by counting (keys unique; rank = # keys strictly greater) ----
    if (tid < cnt) {
        unsigned long long mine = buf[tid];
        int rank = 0;
        #pragma unroll 4
        for (int j = 0; j < cnt; j++) rank += (buf[j] > mine);

        if (rank < TOPK) {
            int   idx = 0x1FFFF - (int)(mine & 0x1FFFF);
            float s   = __uint_as_float((unsigned)(mine >> 17));

            int a   = idx / HW;
            int pix = idx - a * HW;
            int h   = pix / WW;
            int w   = pix - h * WW;

            const float* bb = box + ((size_t)(b * NA + a) * 4) * HW + pix;
            float tx = bb[0];
            float ty = bb[HW];
            float tw = bb[2 * HW];
            float th = bb[3 * HW];

            float cx = (sigmoidf_(tx) + (float)w) / (float)WW;
            float cy = (sigmoidf_(ty) + (float)h) / (float)HH;
            float spw = fmaxf(tw, 0.0f) + log1pf(expf(-fabsf(tw)));
            float sph = fmaxf(th, 0.0f) + log1pf(expf(-fabsf(th)));
            float bwv = anchors[a * 2 + 0] * spw;
            float bhv = anchors[a * 2 + 1] * sph;
            float clsv = (float)g_cls[(size_t)b * NN + idx];

            float* o = out + ((size_t)b * TOPK + rank) * 6;
            o[0] = s;
            o[1] = clsv;
            o[2] = cx;
            o[3] = cy;
            o[4] = bwv;
            o[5] = bhv;
        }
    }
}

// ---------------- launch ----------------
extern "C" void kernel_launch(void* const* d_in, const int* in_sizes, int n_in,
                              void* d_out, int out_size) {
    const float* box     = (const float*)d_in[0];
    const float* obj     = (const float*)d_in[1];
    const float* quality = (const float*)d_in[2];
    const float* cls     = (const float*)d_in[3];
    const float* anchors = (const float*)d_in[4];
    float* out = (float*)d_out;

    zero_hist_kernel<<<(BB * NBINS + 255) / 256, 256>>>();
    score_kernel<<<BB * NN / 4 / 256, 256>>>(obj, quality, cls);
    topk_kernel<<<BB, 1024>>>(box, anchors, out);
}